// round 10
// baseline (speedup 1.0000x reference)
#include <cuda_runtime.h>
#include <cstdint>
#include <cstddef>

// ---------------- problem constants ----------------
#define ND    10000
#define NG    100000
#define EDD   160000
#define EGG   1600000
#define EDT   500000
#define ETD   500000

// ---------------- scratch: __device__ globals, referenced directly in device code ----------------
__device__ float g_drop[(size_t)NG * 128];      // dropout output (max: genes x 128)
__device__ float g_h[(size_t)NG * 64];          // GEMM output
__device__ float g_agg_da[(size_t)ND * 64];     // drug agg (dd branch)
__device__ float g_agg_db[(size_t)ND * 64];     // drug agg (td branch)
__device__ float g_agg_ga[(size_t)NG * 64];     // gene agg (gg branch)
__device__ float g_agg_gb[(size_t)NG * 64];     // gene agg (dt branch)
__device__ float g_cur_drug[(size_t)ND * 64];   // layer-0 drug output
__device__ float g_cur_gene[(size_t)NG * 64];   // layer-0 gene output

// CSR (by target node) per edge type: 0=dd, 1=gg, 2=td, 3=dt
__device__ int g_off_dd[ND + 1], g_off_td[ND + 1];
__device__ int g_off_gg[NG + 1], g_off_dt[NG + 1];
__device__ int g_curs_dd[ND], g_curs_td[ND];
__device__ int g_curs_gg[NG], g_curs_dt[NG];
__device__ int g_src_dd[EDD], g_src_gg[EGG], g_src_td[ETD], g_src_dt[EDT];

// histograms: 0=ht_dd 1=ht_gg 2=ht_td 3=ht_dt (targets), 4=hs_td 5=hs_dt (sources)
__device__ int g_ht_dd[ND], g_ht_td[ND], g_hs_dt[ND];
__device__ int g_ht_gg[NG], g_ht_dt[NG], g_hs_td[NG];

// dinv: 0=dd 1=gg 2=s_td(genes) 3=t_td(drugs) 4=s_dt(drugs) 5=t_dt(genes)
__device__ float g_dinv_dd[ND], g_dinv_t_td[ND], g_dinv_s_dt[ND];
__device__ float g_dinv_gg[NG], g_dinv_s_td[NG], g_dinv_t_dt[NG];

// ---------------- device-side selectors (no cudaGetSymbolAddress anywhere) ----------------
__device__ __forceinline__ int* hist_ptr(int s) {
    switch (s) {
        case 0: return g_ht_dd; case 1: return g_ht_gg; case 2: return g_ht_td;
        case 3: return g_ht_dt; case 4: return g_hs_td; default: return g_hs_dt;
    }
}
__device__ __forceinline__ int hist_n(int s) {
    switch (s) { case 0: case 2: case 5: return ND; default: return NG; }
}
__device__ __forceinline__ int* off_ptr(int et) {
    switch (et) { case 0: return g_off_dd; case 1: return g_off_gg;
                  case 2: return g_off_td; default: return g_off_dt; }
}
__device__ __forceinline__ int* curs_ptr(int et) {
    switch (et) { case 0: return g_curs_dd; case 1: return g_curs_gg;
                  case 2: return g_curs_td; default: return g_curs_dt; }
}
__device__ __forceinline__ int* src_ptr(int et) {
    switch (et) { case 0: return g_src_dd; case 1: return g_src_gg;
                  case 2: return g_src_td; default: return g_src_dt; }
}
__device__ __forceinline__ int tgt_n(int et) {
    switch (et) { case 0: case 2: return ND; default: return NG; }
}
__device__ __forceinline__ float* dinv_ptr(int s) {
    switch (s) {
        case 0: return g_dinv_dd;   case 1: return g_dinv_gg;
        case 2: return g_dinv_s_td; case 3: return g_dinv_t_td;
        case 4: return g_dinv_s_dt; default: return g_dinv_t_dt;
    }
}
__device__ __forceinline__ float* agg_ptr(int s) {
    switch (s) { case 0: return g_agg_da; case 1: return g_agg_db;
                 case 2: return g_agg_ga; default: return g_agg_gb; }
}

// ---------------- threefry2x32 (JAX-compatible) ----------------
__host__ __device__ __forceinline__ uint32_t rotl32(uint32_t v, int r) {
    return (v << r) | (v >> (32 - r));
}
__host__ __device__ __forceinline__ void tf2x32(uint32_t k0, uint32_t k1,
                                                uint32_t x0, uint32_t x1,
                                                uint32_t& o0, uint32_t& o1) {
    uint32_t ks0 = k0, ks1 = k1, ks2 = k0 ^ k1 ^ 0x1BD11BDAu;
    x0 += ks0; x1 += ks1;
#define TFR(r) { x0 += x1; x1 = rotl32(x1, r); x1 ^= x0; }
    TFR(13) TFR(15) TFR(26) TFR(6)
    x0 += ks1; x1 += ks2 + 1u;
    TFR(17) TFR(29) TFR(16) TFR(24)
    x0 += ks2; x1 += ks0 + 2u;
    TFR(13) TFR(15) TFR(26) TFR(6)
    x0 += ks0; x1 += ks1 + 3u;
    TFR(17) TFR(29) TFR(16) TFR(24)
    x0 += ks1; x1 += ks2 + 4u;
    TFR(13) TFR(15) TFR(26) TFR(6)
    x0 += ks2; x1 += ks0 + 5u;
#undef TFR
    o0 = x0; o1 = x1;
}

// ---------------- CSR build kernels ----------------
__global__ void zero_hists_kernel() {
    int i = blockIdx.x * blockDim.x + threadIdx.x;
    if (i < ND) { g_ht_dd[i] = 0; g_ht_td[i] = 0; g_hs_dt[i] = 0; }
    if (i < NG) { g_ht_gg[i] = 0; g_ht_dt[i] = 0; g_hs_td[i] = 0; }
}

__global__ void hist_kernel(const int* __restrict__ ids, int E, int sel) {
    int i = blockIdx.x * blockDim.x + threadIdx.x;
    if (i >= E) return;
    int v = ids[i];
    if ((unsigned)v < (unsigned)hist_n(sel))        // guard: degrade, don't crash
        atomicAdd(&hist_ptr(sel)[v], 1);
}

// single-block exclusive scan; also initializes scatter cursors
__global__ void scan_kernel(int et, int hsel, int n) {
    __shared__ int tsum[1024];
    const int* cnt = hist_ptr(hsel);
    int* off = off_ptr(et);
    int* cur = curs_ptr(et);
    int tid = threadIdx.x;
    int chunk = (n + 1023) >> 10;
    int b = tid * chunk;
    int e = min(b + chunk, n);
    int s = 0;
    for (int i = b; i < e; i++) s += cnt[i];
    tsum[tid] = s;
    __syncthreads();
    for (int o = 1; o < 1024; o <<= 1) {
        int v = (tid >= o) ? tsum[tid - o] : 0;
        __syncthreads();
        tsum[tid] += v;
        __syncthreads();
    }
    int run = (tid > 0) ? tsum[tid - 1] : 0;
    for (int i = b; i < e; i++) {
        off[i] = run; cur[i] = run; run += cnt[i];
    }
    if (tid == 1023) off[n] = tsum[1023];
}

__global__ void dinv_kernel(int hsel, int dsel, int n, int self) {
    int i = blockIdx.x * blockDim.x + threadIdx.x;
    if (i >= n) return;
    int c = hist_ptr(hsel)[i] + self;
    dinv_ptr(dsel)[i] = (c > 0) ? (1.0f / sqrtf((float)c)) : 0.0f;
}

__global__ void scatter_kernel(const int* __restrict__ rows, const int* __restrict__ cols,
                               int E, int et) {
    int i = blockIdx.x * blockDim.x + threadIdx.x;
    if (i >= E) return;
    int c = cols[i];
    if ((unsigned)c >= (unsigned)tgt_n(et)) return;  // guard
    int p = atomicAdd(&curs_ptr(et)[c], 1);
    if (p >= 0 && p < E) src_ptr(et)[p] = rows[i];
}

// ---------------- compute kernels ----------------
// dropout: JAX partitionable threefry; 32-bit bits = o0 ^ o1 (XOR of both output words,
// per _threefry_random_bits_partitionable for bit_width < 64).
// src_sel: 0=drug_x 1=gene_x 2=g_cur_drug 3=g_cur_gene
__global__ void dropout_kernel(const float* __restrict__ drug_x,
                               const float* __restrict__ gene_x,
                               int src_sel, int N, uint32_t k0, uint32_t k1) {
    int i = blockIdx.x * blockDim.x + threadIdx.x;
    if (i >= N) return;
    const float* in = (src_sel == 0) ? drug_x
                    : (src_sel == 1) ? gene_x
                    : (src_sel == 2) ? (const float*)g_cur_drug
                                     : (const float*)g_cur_gene;
    uint32_t o0, o1;
    tf2x32(k0, k1, 0u, (uint32_t)i, o0, o1);
    uint32_t bits = o0 ^ o1;                         // <- the fix
    float u = __uint_as_float((bits >> 9) | 0x3f800000u) - 1.0f;
    g_drop[i] = (u < 0.8f) ? in[i] * 1.25f : 0.0f;
}

// g_h[n,64] = g_drop[n,K] @ W[K,64]; 256 thr, 64 rows/block, K chunked by 64 (33KB smem)
template<int K>
__global__ void gemm_kernel(const float* __restrict__ W, int n) {
    __shared__ float Ws[64 * 64];
    __shared__ float Xs[64 * 65];
    int tid = threadIdx.x;
    int row0 = blockIdx.x << 6;
    int tx = tid & 15, ty = tid >> 4;
    float acc[4][4];
#pragma unroll
    for (int j = 0; j < 4; j++)
#pragma unroll
        for (int q = 0; q < 4; q++) acc[j][q] = 0.0f;

    for (int kc = 0; kc < K; kc += 64) {
        for (int i = tid; i < 64 * 64; i += 256) {
            int k = i >> 6, cc = i & 63;
            Ws[i] = W[(size_t)(kc + k) * 64 + cc];
        }
        for (int i = tid; i < 64 * 64; i += 256) {
            int r = i >> 6, k = i & 63;
            int gr = row0 + r;
            Xs[r * 65 + k] = (gr < n) ? g_drop[(size_t)gr * K + kc + k] : 0.0f;
        }
        __syncthreads();
#pragma unroll 8
        for (int k = 0; k < 64; k++) {
            float4 w = *(const float4*)&Ws[(k << 6) + (tx << 2)];
#pragma unroll
            for (int j = 0; j < 4; j++) {
                float xv = Xs[(ty + (j << 4)) * 65 + k];
                acc[j][0] = fmaf(xv, w.x, acc[j][0]);
                acc[j][1] = fmaf(xv, w.y, acc[j][1]);
                acc[j][2] = fmaf(xv, w.z, acc[j][2]);
                acc[j][3] = fmaf(xv, w.w, acc[j][3]);
            }
        }
        __syncthreads();
    }
#pragma unroll
    for (int j = 0; j < 4; j++) {
        int r = row0 + ty + (j << 4);
        if (r < n) {
            float4 o = make_float4(acc[j][0], acc[j][1], acc[j][2], acc[j][3]);
            *(float4*)&g_h[(size_t)r * 64 + (tx << 2)] = o;
        }
    }
}

// CSR gather: thread = (target node, 16B chunk); no atomics, plain float4 store
__global__ void gather_kernel(int et, int aggsel, int dssel, int dtsel, int self, int n) {
    long long idx = (long long)blockIdx.x * blockDim.x + threadIdx.x;
    if (idx >= (long long)n * 16) return;
    int node = (int)(idx >> 4);
    int c = (int)(idx & 15);
    const int* off = off_ptr(et);
    const int* srcarr = src_ptr(et);
    const float* dinvs = dinv_ptr(dssel);
    const float* dinvt = dinv_ptr(dtsel);
    float* agg = agg_ptr(aggsel);

    int b = off[node], e = off[node + 1];
    float ax = 0.f, ay = 0.f, az = 0.f, aw = 0.f;
    for (int p = b; p < e; p++) {
        int s = __ldg(srcarr + p);
        float ns = __ldg(dinvs + s);
        float4 v = __ldg((const float4*)(g_h + (size_t)s * 64 + (c << 2)));
        ax = fmaf(ns, v.x, ax);
        ay = fmaf(ns, v.y, ay);
        az = fmaf(ns, v.z, az);
        aw = fmaf(ns, v.w, aw);
    }
    float dtv = dinvt[node];
    ax *= dtv; ay *= dtv; az *= dtv; aw *= dtv;
    if (self) {
        float4 v = *(const float4*)(g_h + (size_t)node * 64 + (c << 2));
        float w = dtv * dtv;
        ax = fmaf(w, v.x, ax);
        ay = fmaf(w, v.y, ay);
        az = fmaf(w, v.z, az);
        aw = fmaf(w, v.w, aw);
    }
    *(float4*)(agg + (size_t)node * 64 + (c << 2)) = make_float4(ax, ay, az, aw);
}

// out = l2norm(relu(aggA+bA)) + l2norm(relu(aggB+bB)); one warp per row of 64
// outsel: 0=g_cur_drug, 1=g_cur_gene, 2=out_param
__global__ void combine_kernel(int aselA, const float* __restrict__ bA,
                               int aselB, const float* __restrict__ bB,
                               float* out_param, int outsel, int n) {
    int gw = (blockIdx.x * blockDim.x + threadIdx.x) >> 5;
    int lane = threadIdx.x & 31;
    if (gw >= n) return;
    const float* aggA = agg_ptr(aselA);
    const float* aggB = agg_ptr(aselB);
    float* outp = (outsel == 0) ? g_cur_drug : (outsel == 1) ? g_cur_gene : out_param;
    size_t base = (size_t)gw * 64;
    float a0 = fmaxf(aggA[base + lane] + bA[lane], 0.0f);
    float a1 = fmaxf(aggA[base + lane + 32] + bA[lane + 32], 0.0f);
    float ss = a0 * a0 + a1 * a1;
#pragma unroll
    for (int o = 16; o > 0; o >>= 1) ss += __shfl_xor_sync(0xffffffffu, ss, o);
    float dena = fmaxf(sqrtf(ss), 1e-12f);
    float b0 = fmaxf(aggB[base + lane] + bB[lane], 0.0f);
    float b1 = fmaxf(aggB[base + lane + 32] + bB[lane + 32], 0.0f);
    float ss2 = b0 * b0 + b1 * b1;
#pragma unroll
    for (int o = 16; o > 0; o >>= 1) ss2 += __shfl_xor_sync(0xffffffffu, ss2, o);
    float denb = fmaxf(sqrtf(ss2), 1e-12f);
    outp[base + lane]      = a0 / dena + b0 / denb;
    outp[base + lane + 32] = a1 / dena + b1 / denb;
}

// ---------------- host orchestration ----------------
namespace {
struct Key2 { uint32_t k0, k1; };
inline int cdiv(long long a, int b) { return (int)((a + b - 1) / b); }
}

extern "C" void kernel_launch(void* const* d_in, const int* in_sizes, int n_in,
                              void* d_out, int out_size) {
    // ---- resolve inputs by SIZE, not by assumed position ----
    // sizes: drug_x=1.28M, gene_x=12.8M, ei_dd=320K, ei_gg=3.2M, ei_dt/ei_td=1M,
    //        W0_*=8192, W1_*=4096, b*=64
    int idx_drug = -1, idx_gene = -1, idx_eidd = -1, idx_eigg = -1;
    int idx_1m[2] = {-1, -1}; int n1m = 0;
    int idx_w0[4] = {-1, -1, -1, -1}; int nw0 = 0;
    int idx_w1[4] = {-1, -1, -1, -1}; int nw1 = 0;
    int idx_b[8]  = {-1, -1, -1, -1, -1, -1, -1, -1}; int nb = 0;
    for (int i = 0; i < n_in; i++) {
        int s = in_sizes[i];
        if      (s == ND * 128)  idx_drug = i;
        else if (s == NG * 128)  idx_gene = i;
        else if (s == 2 * EDD)   idx_eidd = i;
        else if (s == 2 * EGG)   idx_eigg = i;
        else if (s == 2 * EDT)   { if (n1m < 2) idx_1m[n1m++] = i; }
        else if (s == 128 * 64)  { if (nw0 < 4) idx_w0[nw0++] = i; }
        else if (s == 64 * 64)   { if (nw1 < 4) idx_w1[nw1++] = i; }
        else if (s == 64)        { if (nb < 8)  idx_b[nb++]  = i; }
    }
    // Layout flag: setup_inputs dict order puts edge indices BEFORE weights
    // (and orders the 1M pair dt,td; biases interleaved per-et: b0,b1).
    // reference() signature order puts them AFTER (1M pair td,dt; biases per-layer).
    bool dict_order = (idx_eidd >= 0 && nw0 > 0 && idx_eidd < idx_w0[0]);

    const float* drug_x = (const float*)d_in[idx_drug];
    const float* gene_x = (const float*)d_in[idx_gene];
    const int* ei_dd = (const int*)d_in[idx_eidd];
    const int* ei_gg = (const int*)d_in[idx_eigg];
    const int* ei_dt = (const int*)d_in[dict_order ? idx_1m[0] : idx_1m[1]];
    const int* ei_td = (const int*)d_in[dict_order ? idx_1m[1] : idx_1m[0]];
    // W0s appear in et order dd,gg,td,dt in both layouts; same for W1s.
    const float* Wl[2][4];
    const float* bl[2][4];
    for (int e = 0; e < 4; e++) {
        Wl[0][e] = (const float*)d_in[idx_w0[e]];
        Wl[1][e] = (const float*)d_in[idx_w1[e]];
        for (int l = 0; l < 2; l++)
            bl[l][e] = (const float*)d_in[idx_b[dict_order ? (e * 2 + l) : (l * 4 + e)]];
    }
    float* out = (float*)d_out;

    // ---- CSR build + degree normalizers (edges identical across layers) ----
    zero_hists_kernel<<<cdiv(NG, 256), 256>>>();
    hist_kernel<<<cdiv(EDD, 256), 256>>>(ei_dd + EDD, EDD, 0);  // dd targets (drugs)
    hist_kernel<<<cdiv(EGG, 256), 256>>>(ei_gg + EGG, EGG, 1);  // gg targets (genes)
    hist_kernel<<<cdiv(ETD, 256), 256>>>(ei_td + ETD, ETD, 2);  // td targets (drugs)
    hist_kernel<<<cdiv(EDT, 256), 256>>>(ei_dt + EDT, EDT, 3);  // dt targets (genes)
    hist_kernel<<<cdiv(ETD, 256), 256>>>(ei_td,       ETD, 4);  // td sources (genes)
    hist_kernel<<<cdiv(EDT, 256), 256>>>(ei_dt,       EDT, 5);  // dt sources (drugs)

    scan_kernel<<<1, 1024>>>(0, 0, ND);
    scan_kernel<<<1, 1024>>>(1, 1, NG);
    scan_kernel<<<1, 1024>>>(2, 2, ND);
    scan_kernel<<<1, 1024>>>(3, 3, NG);

    dinv_kernel<<<cdiv(ND, 256), 256>>>(0, 0, ND, 1);  // dd (self loop +1)
    dinv_kernel<<<cdiv(NG, 256), 256>>>(1, 1, NG, 1);  // gg (self loop +1)
    dinv_kernel<<<cdiv(NG, 256), 256>>>(4, 2, NG, 0);  // td source degree (genes)
    dinv_kernel<<<cdiv(ND, 256), 256>>>(2, 3, ND, 0);  // td target degree (drugs)
    dinv_kernel<<<cdiv(ND, 256), 256>>>(5, 4, ND, 0);  // dt source degree (drugs)
    dinv_kernel<<<cdiv(NG, 256), 256>>>(3, 5, NG, 0);  // dt target degree (genes)

    scatter_kernel<<<cdiv(EDD, 256), 256>>>(ei_dd, ei_dd + EDD, EDD, 0);
    scatter_kernel<<<cdiv(EGG, 256), 256>>>(ei_gg, ei_gg + EGG, EGG, 1);
    scatter_kernel<<<cdiv(ETD, 256), 256>>>(ei_td, ei_td + ETD, ETD, 2);
    scatter_kernel<<<cdiv(EDT, 256), 256>>>(ei_dt, ei_dt + EDT, EDT, 3);

    // ---- JAX dropout keys (threefry, partitionable), computed host-side ----
    // base key(42)=(0,42); folded_l = TF(base,(0,l)); split ks[j] = TF(folded,(0,j))
    Key2 kk[2][4];
    for (int l = 0; l < 2; l++) {
        uint32_t f0, f1;
        tf2x32(0u, 42u, 0u, (uint32_t)l, f0, f1);
        for (int j = 0; j < 4; j++)
            tf2x32(f0, f1, 0u, (uint32_t)j, kk[l][j].k0, kk[l][j].k1);
    }

    // ---- two encoder layers ----
    for (int l = 0; l < 2; l++) {
        int F = (l == 0) ? 128 : 64;
        int sel_d = (l == 0) ? 0 : 2;   // drug input: drug_x or g_cur_drug
        int sel_g = (l == 0) ? 1 : 3;   // gene input: gene_x or g_cur_gene

        const float* Wdd = Wl[l][0]; const float* bdd = bl[l][0];
        const float* Wgg = Wl[l][1]; const float* bgg = bl[l][1];
        const float* Wtd = Wl[l][2]; const float* btd = bl[l][2];
        const float* Wdt = Wl[l][3]; const float* bdt = bl[l][3];

        // d_dd: GCN drug->drug (self loops)
        dropout_kernel<<<cdiv((long long)ND * F, 256), 256>>>(drug_x, gene_x, sel_d,
                                                              ND * F, kk[l][0].k0, kk[l][0].k1);
        if (F == 128) gemm_kernel<128><<<(ND + 63) / 64, 256>>>(Wdd, ND);
        else          gemm_kernel<64><<<(ND + 63) / 64, 256>>>(Wdd, ND);
        gather_kernel<<<cdiv((long long)ND * 16, 256), 256>>>(0, 0, 0, 0, 1, ND);

        // d_td: bipartite gene->drug
        dropout_kernel<<<cdiv((long long)NG * F, 256), 256>>>(drug_x, gene_x, sel_g,
                                                              NG * F, kk[l][1].k0, kk[l][1].k1);
        if (F == 128) gemm_kernel<128><<<(NG + 63) / 64, 256>>>(Wtd, NG);
        else          gemm_kernel<64><<<(NG + 63) / 64, 256>>>(Wtd, NG);
        gather_kernel<<<cdiv((long long)ND * 16, 256), 256>>>(2, 1, 2, 3, 0, ND);

        // g_gg: GCN gene->gene (self loops)
        dropout_kernel<<<cdiv((long long)NG * F, 256), 256>>>(drug_x, gene_x, sel_g,
                                                              NG * F, kk[l][2].k0, kk[l][2].k1);
        if (F == 128) gemm_kernel<128><<<(NG + 63) / 64, 256>>>(Wgg, NG);
        else          gemm_kernel<64><<<(NG + 63) / 64, 256>>>(Wgg, NG);
        gather_kernel<<<cdiv((long long)NG * 16, 256), 256>>>(1, 2, 1, 1, 1, NG);

        // g_dt: bipartite drug->gene
        dropout_kernel<<<cdiv((long long)ND * F, 256), 256>>>(drug_x, gene_x, sel_d,
                                                              ND * F, kk[l][3].k0, kk[l][3].k1);
        if (F == 128) gemm_kernel<128><<<(ND + 63) / 64, 256>>>(Wdt, ND);
        else          gemm_kernel<64><<<(ND + 63) / 64, 256>>>(Wdt, ND);
        gather_kernel<<<cdiv((long long)NG * 16, 256), 256>>>(3, 3, 4, 5, 0, NG);

        // combine per node type
        if (l == 0) {
            combine_kernel<<<cdiv(ND, 8), 256>>>(0, bdd, 1, btd, nullptr, 0, ND);
            combine_kernel<<<cdiv(NG, 8), 256>>>(2, bgg, 3, bdt, nullptr, 1, NG);
        } else {
            combine_kernel<<<cdiv(ND, 8), 256>>>(0, bdd, 1, btd, out, 2, ND);
            combine_kernel<<<cdiv(NG, 8), 256>>>(2, bgg, 3, bdt, out + (size_t)ND * 64, 2, NG);
        }
    }
}

// round 12
// speedup vs baseline: 1.5012x; 1.5012x over previous
#include <cuda_runtime.h>
#include <cstdint>
#include <cstddef>

// ---------------- problem constants ----------------
#define ND    10000
#define NG    100000
#define EDD   160000
#define EGG   1600000
#define EDT   500000
#define ETD   500000

// ---------------- scratch: __device__ globals ----------------
__device__ float g_h0[(size_t)ND * 64];         // dd branch GEMM out (drug sources)
__device__ float g_h1[(size_t)NG * 64];         // td branch GEMM out (gene sources)
__device__ float g_h2[(size_t)NG * 64];         // gg branch GEMM out (gene sources)
__device__ float g_h3[(size_t)ND * 64];         // dt branch GEMM out (drug sources)
__device__ float g_agg_da[(size_t)ND * 64];     // drug agg (dd)
__device__ float g_agg_db[(size_t)ND * 64];     // drug agg (td)
__device__ float g_agg_ga[(size_t)NG * 64];     // gene agg (gg)
__device__ float g_agg_gb[(size_t)NG * 64];     // gene agg (dt)
__device__ float g_cur_drug[(size_t)ND * 64];   // layer-0 drug output
__device__ float g_cur_gene[(size_t)NG * 64];   // layer-0 gene output

// CSR (by target node) per edge type: 0=dd, 1=gg, 2=td, 3=dt
__device__ int g_off_dd[ND + 1], g_off_td[ND + 1];
__device__ int g_off_gg[NG + 1], g_off_dt[NG + 1];
__device__ int g_curs_dd[ND], g_curs_td[ND];
__device__ int g_curs_gg[NG], g_curs_dt[NG];
__device__ int g_src_dd[EDD], g_src_gg[EGG], g_src_td[ETD], g_src_dt[EDT];

// histograms
__device__ int g_ht_dd[ND], g_ht_td[ND], g_hs_dt[ND];
__device__ int g_ht_gg[NG], g_ht_dt[NG], g_hs_td[NG];

// dinv: 0=dd 1=gg 2=s_td(genes) 3=t_td(drugs) 4=s_dt(drugs) 5=t_dt(genes)
__device__ float g_dinv_dd[ND], g_dinv_t_td[ND], g_dinv_s_dt[ND];
__device__ float g_dinv_gg[NG], g_dinv_s_td[NG], g_dinv_t_dt[NG];

// ---------------- device-side selectors ----------------
__device__ __forceinline__ int* hist_ptr(int s) {
    switch (s) {
        case 0: return g_ht_dd; case 1: return g_ht_gg; case 2: return g_ht_td;
        case 3: return g_ht_dt; case 4: return g_hs_td; default: return g_hs_dt;
    }
}
__device__ __forceinline__ int* off_ptr(int et) {
    switch (et) { case 0: return g_off_dd; case 1: return g_off_gg;
                  case 2: return g_off_td; default: return g_off_dt; }
}
__device__ __forceinline__ int* curs_ptr(int et) {
    switch (et) { case 0: return g_curs_dd; case 1: return g_curs_gg;
                  case 2: return g_curs_td; default: return g_curs_dt; }
}
__device__ __forceinline__ int* src_ptr(int et) {
    switch (et) { case 0: return g_src_dd; case 1: return g_src_gg;
                  case 2: return g_src_td; default: return g_src_dt; }
}
__device__ __forceinline__ int tgt_n(int et) {
    switch (et) { case 0: case 2: return ND; default: return NG; }
}
__device__ __forceinline__ float* dinv_ptr(int s) {
    switch (s) {
        case 0: return g_dinv_dd;   case 1: return g_dinv_gg;
        case 2: return g_dinv_s_td; case 3: return g_dinv_t_td;
        case 4: return g_dinv_s_dt; default: return g_dinv_t_dt;
    }
}
__device__ __forceinline__ float* agg_ptr(int s) {
    switch (s) { case 0: return g_agg_da; case 1: return g_agg_db;
                 case 2: return g_agg_ga; default: return g_agg_gb; }
}

// ---------------- threefry2x32 (JAX-compatible) ----------------
__host__ __device__ __forceinline__ uint32_t rotl32(uint32_t v, int r) {
    return (v << r) | (v >> (32 - r));
}
__host__ __device__ __forceinline__ void tf2x32(uint32_t k0, uint32_t k1,
                                                uint32_t x0, uint32_t x1,
                                                uint32_t& o0, uint32_t& o1) {
    uint32_t ks0 = k0, ks1 = k1, ks2 = k0 ^ k1 ^ 0x1BD11BDAu;
    x0 += ks0; x1 += ks1;
#define TFR(r) { x0 += x1; x1 = rotl32(x1, r); x1 ^= x0; }
    TFR(13) TFR(15) TFR(26) TFR(6)
    x0 += ks1; x1 += ks2 + 1u;
    TFR(17) TFR(29) TFR(16) TFR(24)
    x0 += ks2; x1 += ks0 + 2u;
    TFR(13) TFR(15) TFR(26) TFR(6)
    x0 += ks0; x1 += ks1 + 3u;
    TFR(17) TFR(29) TFR(16) TFR(24)
    x0 += ks1; x1 += ks2 + 4u;
    TFR(13) TFR(15) TFR(26) TFR(6)
    x0 += ks2; x1 += ks0 + 5u;
#undef TFR
    o0 = x0; o1 = x1;
}

// ---------------- CSR build kernels (fused) ----------------
__global__ void zero_hists_kernel() {
    int i = blockIdx.x * blockDim.x + threadIdx.x;
    if (i < ND) { g_ht_dd[i] = 0; g_ht_td[i] = 0; g_hs_dt[i] = 0; }
    if (i < NG) { g_ht_gg[i] = 0; g_ht_dt[i] = 0; g_hs_td[i] = 0; }
}

// One launch over all 6 id streams (3.76M entries).
__global__ void hist_all_kernel(const int* __restrict__ t_dd, const int* __restrict__ t_gg,
                                const int* __restrict__ t_td, const int* __restrict__ t_dt,
                                const int* __restrict__ s_td, const int* __restrict__ s_dt) {
    int i = blockIdx.x * blockDim.x + threadIdx.x;
    const int B0 = EDD, B1 = B0 + EGG, B2 = B1 + ETD, B3 = B2 + EDT,
              B4 = B3 + ETD, B5 = B4 + EDT;
    int v, nmax; int* hist;
    if (i < B0)      { v = t_dd[i];      hist = g_ht_dd; nmax = ND; }
    else if (i < B1) { v = t_gg[i - B0]; hist = g_ht_gg; nmax = NG; }
    else if (i < B2) { v = t_td[i - B1]; hist = g_ht_td; nmax = ND; }
    else if (i < B3) { v = t_dt[i - B2]; hist = g_ht_dt; nmax = NG; }
    else if (i < B4) { v = s_td[i - B3]; hist = g_hs_td; nmax = NG; }
    else if (i < B5) { v = s_dt[i - B4]; hist = g_hs_dt; nmax = ND; }
    else return;
    if ((unsigned)v < (unsigned)nmax) atomicAdd(&hist[v], 1);
}

// 4 concurrent single-block scans (blockIdx.x = edge type); inits cursors too
__global__ void scan4_kernel() {
    __shared__ int tsum[1024];
    int et = blockIdx.x;                    // hsel == et for targets 0..3
    int n = tgt_n(et);
    const int* cnt = hist_ptr(et);
    int* off = off_ptr(et);
    int* cur = curs_ptr(et);
    int tid = threadIdx.x;
    int chunk = (n + 1023) >> 10;
    int b = tid * chunk;
    int e = min(b + chunk, n);
    int s = 0;
    for (int i = b; i < e; i++) s += cnt[i];
    tsum[tid] = s;
    __syncthreads();
    for (int o = 1; o < 1024; o <<= 1) {
        int v = (tid >= o) ? tsum[tid - o] : 0;
        __syncthreads();
        tsum[tid] += v;
        __syncthreads();
    }
    int run = (tid > 0) ? tsum[tid - 1] : 0;
    for (int i = b; i < e; i++) {
        off[i] = run; cur[i] = run; run += cnt[i];
    }
    if (tid == 1023) off[n] = tsum[1023];
}

__device__ __forceinline__ float dinv_of(int c) {
    return (c > 0) ? (1.0f / sqrtf((float)c)) : 0.0f;
}

__global__ void dinv_all_kernel() {
    int i = blockIdx.x * blockDim.x + threadIdx.x;
    if (i < ND) {
        g_dinv_dd[i]   = dinv_of(g_ht_dd[i] + 1);   // self loop
        g_dinv_t_td[i] = dinv_of(g_ht_td[i]);
        g_dinv_s_dt[i] = dinv_of(g_hs_dt[i]);
    }
    if (i < NG) {
        g_dinv_gg[i]   = dinv_of(g_ht_gg[i] + 1);   // self loop
        g_dinv_s_td[i] = dinv_of(g_hs_td[i]);
        g_dinv_t_dt[i] = dinv_of(g_ht_dt[i]);
    }
}

// One launch over all 4 edge lists (2.76M edges): sort sources by target
__global__ void scatter_all_kernel(const int* __restrict__ ei_dd, const int* __restrict__ ei_gg,
                                   const int* __restrict__ ei_td, const int* __restrict__ ei_dt) {
    int i = blockIdx.x * blockDim.x + threadIdx.x;
    const int B0 = EDD, B1 = B0 + EGG, B2 = B1 + ETD, B3 = B2 + EDT;
    int et, e, E; const int* ei;
    if (i < B0)      { et = 0; e = i;      ei = ei_dd; E = EDD; }
    else if (i < B1) { et = 1; e = i - B0; ei = ei_gg; E = EGG; }
    else if (i < B2) { et = 2; e = i - B1; ei = ei_td; E = ETD; }
    else if (i < B3) { et = 3; e = i - B2; ei = ei_dt; E = EDT; }
    else return;
    int c = ei[E + e];                          // target
    if ((unsigned)c >= (unsigned)tgt_n(et)) return;
    int p = atomicAdd(&curs_ptr(et)[c], 1);
    if (p >= 0 && p < E) src_ptr(et)[p] = ei[e];  // source
}

// ---------------- fused dropout + 4-branch GEMM ----------------
// blocks [0,BD): dd (drug in, ->g_h0); [BD,BD+BG): td (gene in, ->g_h1);
// [BD+BG,BD+2BG): gg (gene in, ->g_h2); rest: dt (drug in, ->g_h3)
struct GemmArgs {
    const float* W[4];
    uint32_t k0[4], k1[4];
};

template<int K>
__global__ __launch_bounds__(256)
void gemm4_kernel(const float* __restrict__ drug_x, const float* __restrict__ gene_x,
                  int layer, GemmArgs a) {
    __shared__ float Ws[64 * 64];
    __shared__ float Xs[64 * 65];
    const int BD = (ND + 63) / 64, BG = (NG + 63) / 64;
    int bid = blockIdx.x;
    int br, rb, n;
    if (bid < BD)               { br = 0; rb = bid;                 n = ND; }
    else if (bid < BD + BG)     { br = 1; rb = bid - BD;            n = NG; }
    else if (bid < BD + 2 * BG) { br = 2; rb = bid - BD - BG;       n = NG; }
    else                        { br = 3; rb = bid - BD - 2 * BG;   n = ND; }
    int row0 = rb << 6;
    bool drug_in = (br == 0 || br == 3);
    const float* X = drug_in ? (layer ? (const float*)g_cur_drug : drug_x)
                             : (layer ? (const float*)g_cur_gene : gene_x);
    float* Hm = (br == 0) ? g_h0 : (br == 1) ? g_h1 : (br == 2) ? g_h2 : g_h3;
    const float* W = a.W[br];
    uint32_t k0 = a.k0[br], k1 = a.k1[br];

    int tid = threadIdx.x;
    int tx = tid & 15, ty = tid >> 4;
    float acc[4][4];
#pragma unroll
    for (int j = 0; j < 4; j++)
#pragma unroll
        for (int q = 0; q < 4; q++) acc[j][q] = 0.0f;

    for (int kc = 0; kc < K; kc += 64) {
        for (int i = tid; i < 64 * 64; i += 256) {
            int k = i >> 6, cc = i & 63;
            Ws[i] = W[(size_t)(kc + k) * 64 + cc];
        }
        // X tile load with fused JAX-threefry dropout (bits = o0 ^ o1)
        for (int i = tid; i < 64 * 64; i += 256) {
            int r = i >> 6, k = i & 63;
            int gr = row0 + r;
            float v = 0.0f;
            if (gr < n) {
                uint32_t idx = (uint32_t)gr * (uint32_t)K + (uint32_t)(kc + k);
                uint32_t o0, o1;
                tf2x32(k0, k1, 0u, idx, o0, o1);
                uint32_t bits = o0 ^ o1;
                float u = __uint_as_float((bits >> 9) | 0x3f800000u) - 1.0f;
                float xv = X[idx];
                v = (u < 0.8f) ? xv * 1.25f : 0.0f;
            }
            Xs[r * 65 + k] = v;
        }
        __syncthreads();
#pragma unroll 8
        for (int k = 0; k < 64; k++) {
            float4 w = *(const float4*)&Ws[(k << 6) + (tx << 2)];
#pragma unroll
            for (int j = 0; j < 4; j++) {
                float xv = Xs[(ty + (j << 4)) * 65 + k];
                acc[j][0] = fmaf(xv, w.x, acc[j][0]);
                acc[j][1] = fmaf(xv, w.y, acc[j][1]);
                acc[j][2] = fmaf(xv, w.z, acc[j][2]);
                acc[j][3] = fmaf(xv, w.w, acc[j][3]);
            }
        }
        __syncthreads();
    }
#pragma unroll
    for (int j = 0; j < 4; j++) {
        int r = row0 + ty + (j << 4);
        if (r < n) {
            float4 o = make_float4(acc[j][0], acc[j][1], acc[j][2], acc[j][3]);
            *(float4*)&Hm[(size_t)r * 64 + (tx << 2)] = o;
        }
    }
}

// ---------------- fused 4-branch CSR gather ----------------
// thread = (target node, 16B chunk) across all 4 branches
__global__ void gather4_kernel() {
    int idx = blockIdx.x * blockDim.x + threadIdx.x;
    const int S0 = ND * 16, S1 = 2 * ND * 16, S2 = (2 * ND + NG) * 16,
              TOT = (2 * ND + 2 * NG) * 16;
    if (idx >= TOT) return;
    int local, et, aggsel, dssel, dtsel, self;
    const float* Hm;
    if (idx < S0)      { local = idx;      et = 0; aggsel = 0; dssel = 0; dtsel = 0; self = 1; Hm = g_h0; }
    else if (idx < S1) { local = idx - S0; et = 2; aggsel = 1; dssel = 2; dtsel = 3; self = 0; Hm = g_h1; }
    else if (idx < S2) { local = idx - S1; et = 1; aggsel = 2; dssel = 1; dtsel = 1; self = 1; Hm = g_h2; }
    else               { local = idx - S2; et = 3; aggsel = 3; dssel = 4; dtsel = 5; self = 0; Hm = g_h3; }
    int node = local >> 4, c = local & 15;
    const int* off = off_ptr(et);
    const int* srcarr = src_ptr(et);
    const float* dinvs = dinv_ptr(dssel);
    const float* dinvt = dinv_ptr(dtsel);
    float* agg = agg_ptr(aggsel);

    int b = off[node], e = off[node + 1];
    float ax = 0.f, ay = 0.f, az = 0.f, aw = 0.f;
    for (int p = b; p < e; p++) {
        int s = __ldg(srcarr + p);
        float ns = __ldg(dinvs + s);
        float4 v = __ldg((const float4*)(Hm + (size_t)s * 64 + (c << 2)));
        ax = fmaf(ns, v.x, ax);
        ay = fmaf(ns, v.y, ay);
        az = fmaf(ns, v.z, az);
        aw = fmaf(ns, v.w, aw);
    }
    float dtv = dinvt[node];
    ax *= dtv; ay *= dtv; az *= dtv; aw *= dtv;
    if (self) {
        float4 v = *(const float4*)(Hm + (size_t)node * 64 + (c << 2));
        float w = dtv * dtv;
        ax = fmaf(w, v.x, ax);
        ay = fmaf(w, v.y, ay);
        az = fmaf(w, v.z, az);
        aw = fmaf(w, v.w, aw);
    }
    *(float4*)(agg + (size_t)node * 64 + (c << 2)) = make_float4(ax, ay, az, aw);
}

// ---------------- fused combine (both node types) ----------------
// warp per node; warps [0,ND) = drugs, [ND,ND+NG) = genes
__global__ void combine2_kernel(const float* __restrict__ bdd, const float* __restrict__ btd,
                                const float* __restrict__ bgg, const float* __restrict__ bdt,
                                float* out_drug, float* out_gene, int to_global) {
    int gw = (blockIdx.x * blockDim.x + threadIdx.x) >> 5;
    int lane = threadIdx.x & 31;
    if (gw >= ND + NG) return;
    const float *aggA, *aggB, *bA, *bB;
    float* outp;
    int row;
    if (gw < ND) {
        aggA = g_agg_da; aggB = g_agg_db; bA = bdd; bB = btd;
        outp = to_global ? g_cur_drug : out_drug; row = gw;
    } else {
        aggA = g_agg_ga; aggB = g_agg_gb; bA = bgg; bB = bdt;
        outp = to_global ? g_cur_gene : out_gene; row = gw - ND;
    }
    size_t base = (size_t)row * 64;
    float a0 = fmaxf(aggA[base + lane] + bA[lane], 0.0f);
    float a1 = fmaxf(aggA[base + lane + 32] + bA[lane + 32], 0.0f);
    float ss = a0 * a0 + a1 * a1;
#pragma unroll
    for (int o = 16; o > 0; o >>= 1) ss += __shfl_xor_sync(0xffffffffu, ss, o);
    float dena = fmaxf(sqrtf(ss), 1e-12f);
    float b0 = fmaxf(aggB[base + lane] + bB[lane], 0.0f);
    float b1 = fmaxf(aggB[base + lane + 32] + bB[lane + 32], 0.0f);
    float ss2 = b0 * b0 + b1 * b1;
#pragma unroll
    for (int o = 16; o > 0; o >>= 1) ss2 += __shfl_xor_sync(0xffffffffu, ss2, o);
    float denb = fmaxf(sqrtf(ss2), 1e-12f);
    outp[base + lane]      = a0 / dena + b0 / denb;
    outp[base + lane + 32] = a1 / dena + b1 / denb;
}

// ---------------- host orchestration ----------------
namespace {
struct Key2 { uint32_t k0, k1; };
inline int cdiv(long long a, int b) { return (int)((a + b - 1) / b); }
}

extern "C" void kernel_launch(void* const* d_in, const int* in_sizes, int n_in,
                              void* d_out, int out_size) {
    // ---- resolve inputs by SIZE (confirmed working in round 9) ----
    int idx_drug = -1, idx_gene = -1, idx_eidd = -1, idx_eigg = -1;
    int idx_1m[2] = {-1, -1}; int n1m = 0;
    int idx_w0[4] = {-1, -1, -1, -1}; int nw0 = 0;
    int idx_w1[4] = {-1, -1, -1, -1}; int nw1 = 0;
    int idx_b[8]  = {-1, -1, -1, -1, -1, -1, -1, -1}; int nb = 0;
    for (int i = 0; i < n_in; i++) {
        int s = in_sizes[i];
        if      (s == ND * 128)  idx_drug = i;
        else if (s == NG * 128)  idx_gene = i;
        else if (s == 2 * EDD)   idx_eidd = i;
        else if (s == 2 * EGG)   idx_eigg = i;
        else if (s == 2 * EDT)   { if (n1m < 2) idx_1m[n1m++] = i; }
        else if (s == 128 * 64)  { if (nw0 < 4) idx_w0[nw0++] = i; }
        else if (s == 64 * 64)   { if (nw1 < 4) idx_w1[nw1++] = i; }
        else if (s == 64)        { if (nb < 8)  idx_b[nb++]  = i; }
    }
    bool dict_order = (idx_eidd >= 0 && nw0 > 0 && idx_eidd < idx_w0[0]);

    const float* drug_x = (const float*)d_in[idx_drug];
    const float* gene_x = (const float*)d_in[idx_gene];
    const int* ei_dd = (const int*)d_in[idx_eidd];
    const int* ei_gg = (const int*)d_in[idx_eigg];
    const int* ei_dt = (const int*)d_in[dict_order ? idx_1m[0] : idx_1m[1]];
    const int* ei_td = (const int*)d_in[dict_order ? idx_1m[1] : idx_1m[0]];
    const float* Wl[2][4];
    const float* bl[2][4];
    for (int e = 0; e < 4; e++) {
        Wl[0][e] = (const float*)d_in[idx_w0[e]];
        Wl[1][e] = (const float*)d_in[idx_w1[e]];
        for (int l = 0; l < 2; l++)
            bl[l][e] = (const float*)d_in[idx_b[dict_order ? (e * 2 + l) : (l * 4 + e)]];
    }
    float* out = (float*)d_out;

    // ---- CSR build (5 launches) ----
    const long long TOTH = (long long)EDD + EGG + ETD + EDT + ETD + EDT; // 3.76M
    const long long TOTS = (long long)EDD + EGG + ETD + EDT;             // 2.76M
    zero_hists_kernel<<<cdiv(NG, 256), 256>>>();
    hist_all_kernel<<<cdiv(TOTH, 256), 256>>>(ei_dd + EDD, ei_gg + EGG, ei_td + ETD,
                                              ei_dt + EDT, ei_td, ei_dt);
    scan4_kernel<<<4, 1024>>>();
    dinv_all_kernel<<<cdiv(NG, 256), 256>>>();
    scatter_all_kernel<<<cdiv(TOTS, 256), 256>>>(ei_dd, ei_gg, ei_td, ei_dt);

    // ---- JAX dropout keys (threefry, partitionable), host-side ----
    Key2 kk[2][4];
    for (int l = 0; l < 2; l++) {
        uint32_t f0, f1;
        tf2x32(0u, 42u, 0u, (uint32_t)l, f0, f1);
        for (int j = 0; j < 4; j++)
            tf2x32(f0, f1, 0u, (uint32_t)j, kk[l][j].k0, kk[l][j].k1);
    }

    // ---- two encoder layers: 3 launches each ----
    const int BD = (ND + 63) / 64, BG = (NG + 63) / 64;
    const int GEMM_GRID = 2 * (BD + BG);                 // 3440
    const long long TOTG = (long long)(2 * ND + 2 * NG) * 16;  // 3.52M
    const long long TOTC = (long long)(ND + NG) * 32;

    for (int l = 0; l < 2; l++) {
        GemmArgs ga;
        for (int e = 0; e < 4; e++) {
            ga.W[e]  = Wl[l][e];
            // branch order in gemm4: 0=dd(key0), 1=td(key1), 2=gg(key2), 3=dt(key3)
        }
        ga.k0[0] = kk[l][0].k0; ga.k1[0] = kk[l][0].k1;   // dd: drug dropout
        ga.k0[1] = kk[l][1].k0; ga.k1[1] = kk[l][1].k1;   // td: gene dropout
        ga.k0[2] = kk[l][2].k0; ga.k1[2] = kk[l][2].k1;   // gg: gene dropout
        ga.k0[3] = kk[l][3].k0; ga.k1[3] = kk[l][3].k1;   // dt: drug dropout
        // W order in gemm4 branches: 0=Wdd, 1=Wtd, 2=Wgg, 3=Wdt
        ga.W[0] = Wl[l][0]; ga.W[1] = Wl[l][2]; ga.W[2] = Wl[l][1]; ga.W[3] = Wl[l][3];

        if (l == 0) gemm4_kernel<128><<<GEMM_GRID, 256>>>(drug_x, gene_x, 0, ga);
        else        gemm4_kernel<64><<<GEMM_GRID, 256>>>(drug_x, gene_x, 1, ga);

        gather4_kernel<<<cdiv(TOTG, 256), 256>>>();

        if (l == 0)
            combine2_kernel<<<cdiv(TOTC, 256), 256>>>(bl[l][0], bl[l][2], bl[l][1], bl[l][3],
                                                      nullptr, nullptr, 1);
        else
            combine2_kernel<<<cdiv(TOTC, 256), 256>>>(bl[l][0], bl[l][2], bl[l][1], bl[l][3],
                                                      out, out + (size_t)ND * 64, 0);
    }
}